// round 13
// baseline (speedup 1.0000x reference)
#include <cuda_runtime.h>
#include <cuda_fp16.h>

#define N_USERS 100000
#define N_ITEMS 50000
#define N_TOTAL (N_USERS + N_ITEMS)
#define D 64
#define DH 32                 // half2 per row
#define HYPER_X 0.5f
#define MAX_NNZ 2000000
#define MAX_SAMPLED 32768
#define SCAN_BLK 1024
#define SCAN_NB ((N_TOTAL + SCAN_BLK - 1) / SCAN_BLK)   // 147

// fp16 feature tables: one 64-dim row = 32 half2 = 128B = one L2 line
__device__ __half2 g_h0[N_TOTAL * DH];   // converted input embeddings
__device__ __half2 g_h1[N_TOTAL * DH];
__device__ __half2 g_h2[N_TOTAL * DH];
__device__ __half2 g_h3[N_TOTAL * DH];

// CSR scratch (g_csr 16B-aligned so edge pairs load as one int4)
__device__ int  g_deg[N_TOTAL];
__device__ int  g_offs[N_TOTAL + 1];
__device__ int  g_rank[MAX_NNZ];         // per-edge within-row rank (from hist atomics)
__device__ int  g_blocksum[SCAN_NB];     // lookback slots: 0 = not ready, else agg+1
__device__ __align__(16) int2 g_csr[MAX_NNZ];   // {col, float_as_int(val)}

// sampled-row dedup for masked layer 3
__device__ int g_flag[N_TOTAL];
__device__ int g_rowlist[MAX_SAMPLED];
__device__ int g_rowcount;

// ---------------------------------------------------------------------------
// convert embeddings fp32 -> half2 table, and zero deg/flag/blocksum/rowcount
// ---------------------------------------------------------------------------
__global__ void convert_zero_kernel(const float2* __restrict__ eu,
                                    const float2* __restrict__ ei) {
    const int total = N_TOTAL * DH;
    for (int i = blockIdx.x * blockDim.x + threadIdx.x; i < total;
         i += gridDim.x * blockDim.x) {
        float2 v = (i < N_USERS * DH) ? __ldg(&eu[i]) : __ldg(&ei[i - N_USERS * DH]);
        g_h0[i] = __floats2half2_rn(v.x, v.y);
    }
    for (int i = blockIdx.x * blockDim.x + threadIdx.x; i < N_TOTAL;
         i += gridDim.x * blockDim.x) {
        g_deg[i] = 0;
        g_flag[i] = 0;
    }
    int i = blockIdx.x * blockDim.x + threadIdx.x;
    if (i < SCAN_NB) g_blocksum[i] = 0;
    if (i == 0) g_rowcount = 0;
}

// ---------------------------------------------------------------------------
// fused: mark sampled rows (dedup) + degree histogram. The histogram atomic's
// return value IS the edge's within-row rank -> store it (coalesced int4).
// ---------------------------------------------------------------------------
__global__ void mark_hist_kernel(const int* __restrict__ users,
                                 const int* __restrict__ items, int B,
                                 const int* __restrict__ row, int nnz) {
    int i = blockIdx.x * blockDim.x + threadIdx.x;
    if (i < B) {
        int u = users[i];
        if (atomicExch(&g_flag[u], 1) == 0) {
            int p = atomicAdd(&g_rowcount, 1);
            g_rowlist[p] = u;
        }
        int it = N_USERS + items[i];
        if (atomicExch(&g_flag[it], 1) == 0) {
            int p = atomicAdd(&g_rowcount, 1);
            g_rowlist[p] = it;
        }
    }
    int base = 4 * i;
    if (base + 3 < nnz) {
        int4 r4 = ((const int4*)row)[i];
        int4 k4;
        k4.x = atomicAdd(&g_deg[r4.x], 1);
        k4.y = atomicAdd(&g_deg[r4.y], 1);
        k4.z = atomicAdd(&g_deg[r4.z], 1);
        k4.w = atomicAdd(&g_deg[r4.w], 1);
        ((int4*)g_rank)[i] = k4;
    } else {
        for (int e = base; e < nnz; e++)
            g_rank[e] = atomicAdd(&g_deg[row[e]], 1);
    }
}

// ---------------------------------------------------------------------------
// single-kernel exclusive scan with decoupled lookback (147 blocks, 1 wave)
// ---------------------------------------------------------------------------
__device__ __forceinline__ int block_exscan(int v, int* sh) {
    int lane = threadIdx.x & 31, wid = threadIdx.x >> 5;
    int incl = v;
    #pragma unroll
    for (int o = 1; o < 32; o <<= 1) {
        int n = __shfl_up_sync(0xffffffffu, incl, o);
        if (lane >= o) incl += n;
    }
    if (lane == 31) sh[wid] = incl;
    __syncthreads();
    if (wid == 0) {
        int w = sh[lane];
        #pragma unroll
        for (int o = 1; o < 32; o <<= 1) {
            int n = __shfl_up_sync(0xffffffffu, w, o);
            if (lane >= o) w += n;
        }
        sh[lane] = w;
    }
    __syncthreads();
    int warpoff = (wid > 0) ? sh[wid - 1] : 0;
    return warpoff + incl - v;
}

__global__ void scan_lookback_kernel() {
    __shared__ int sh[32];
    __shared__ int base_sh;
    const int t = threadIdx.x;
    const int i = blockIdx.x * SCAN_BLK + t;
    int v = (i < N_TOTAL) ? g_deg[i] : 0;
    int ex = block_exscan(v, sh);

    if (t == SCAN_BLK - 1) {
        atomicExch(&g_blocksum[blockIdx.x], ex + v + 1);
    }
    if (t == 0) base_sh = 0;
    __syncthreads();

    if (t < blockIdx.x) {
        int a;
        do { a = atomicAdd(&g_blocksum[t], 0); } while (a == 0);
        atomicAdd(&base_sh, a - 1);
    }
    __syncthreads();

    int exg = ex + base_sh;
    if (i < N_TOTAL) {
        g_offs[i] = exg;
        if (i == N_TOTAL - 1) g_offs[N_TOTAL] = exg + v;
    }
}

// ---------------------------------------------------------------------------
// CSR fill, ATOMIC-FREE: pos = offs[row] + rank (rank captured during hist).
// Coalesced int4/float4 loads, one 4B offs gather, scattered 8B stores.
// ---------------------------------------------------------------------------
__global__ void fill_kernel(const int* __restrict__ row,
                            const int* __restrict__ col,
                            const float* __restrict__ val, int nnz) {
    int t = blockIdx.x * blockDim.x + threadIdx.x;
    int base = 4 * t;
    if (base + 3 < nnz) {
        int4   r4 = ((const int4*)row)[t];
        int4   c4 = ((const int4*)col)[t];
        float4 v4 = ((const float4*)val)[t];
        int4   k4 = ((const int4*)g_rank)[t];
        int p0 = __ldg(&g_offs[r4.x]) + k4.x;
        int p1 = __ldg(&g_offs[r4.y]) + k4.y;
        int p2 = __ldg(&g_offs[r4.z]) + k4.z;
        int p3 = __ldg(&g_offs[r4.w]) + k4.w;
        g_csr[p0] = make_int2(c4.x, __float_as_int(v4.x));
        g_csr[p1] = make_int2(c4.y, __float_as_int(v4.y));
        g_csr[p2] = make_int2(c4.z, __float_as_int(v4.z));
        g_csr[p3] = make_int2(c4.w, __float_as_int(v4.w));
    } else {
        for (int e = base; e < nnz; e++) {
            int p = __ldg(&g_offs[row[e]]) + g_rank[e];
            g_csr[p] = make_int2(col[e], __float_as_int(val[e]));
        }
    }
}

// ---------------------------------------------------------------------------
// SpMM (fp16 storage, fp32 accumulate): 1 warp per row, one half2 per lane.
// Head-peeled so the main loop reads edge PAIRS as one aligned int4 meta load
// (3 LDG per 2 edges instead of 4). Scalar tail for odd remainder.
// ---------------------------------------------------------------------------
__device__ __forceinline__ void spmm_row_half(
        int r, int lane,
        const __half2* __restrict__ x, __half2* __restrict__ y) {
    int beg = g_offs[r];
    const int end = g_offs[r + 1];

    float ax = 0.f, ay = 0.f;
    if ((beg & 1) && beg < end) {     // head peel -> even alignment
        int2 m = g_csr[beg];
        float2 xv = __half22float2(x[(long)m.x * DH + lane]);
        float v = __int_as_float(m.y);
        ax += v * xv.x; ay += v * xv.y;
        beg++;
    }
    int j = beg;
    for (; j + 1 < end; j += 2) {
        int4 mm = *(const int4*)&g_csr[j];          // one 16B meta load, 2 edges
        float2 x0 = __half22float2(x[(long)mm.x * DH + lane]);
        float2 x1 = __half22float2(x[(long)mm.z * DH + lane]);
        float v0 = __int_as_float(mm.y);
        float v1 = __int_as_float(mm.w);
        ax += v0 * x0.x; ay += v0 * x0.y;
        ax += v1 * x1.x; ay += v1 * x1.y;
    }
    if (j < end) {
        int2 m = g_csr[j];
        float2 xv = __half22float2(x[(long)m.x * DH + lane]);
        float v = __int_as_float(m.y);
        ax += v * xv.x; ay += v * xv.y;
    }
    y[(long)r * DH + lane] = __floats2half2_rn(ax, ay);
}

__global__ void spmm_h_kernel(const __half2* __restrict__ x,
                              __half2* __restrict__ y) {
    const int lane = threadIdx.x & 31;
    const int r = (blockIdx.x * blockDim.x + threadIdx.x) >> 5;
    if (r >= N_TOTAL) return;
    spmm_row_half(r, lane, x, y);
}

// layer 3: only sampled rows
__global__ void spmm_list_kernel(const __half2* __restrict__ x,
                                 __half2* __restrict__ y) {
    const int lane = threadIdx.x & 31;
    const int idx = (blockIdx.x * blockDim.x + threadIdx.x) >> 5;
    if (idx >= g_rowcount) return;
    const int r = g_rowlist[idx];
    spmm_row_half(r, lane, x, y);
}

// ---------------------------------------------------------------------------
// Epilogue: e0 from fp32 inputs (exact), e1..e3 from half tables.
// ---------------------------------------------------------------------------
#define SAMPLES_PER_BLOCK 8

__device__ __forceinline__ float sigmoidf_(float x) {
    return 1.0f / (1.0f + expf(-x));
}

__global__ void epilogue_kernel(const float* __restrict__ emb_user,
                                const float* __restrict__ emb_item,
                                const float* __restrict__ w_user,
                                const float* __restrict__ w_item,
                                const float* __restrict__ xij_emb1,
                                const float* __restrict__ xij_emb0,
                                const int* __restrict__ users,
                                const int* __restrict__ items,
                                const int* __restrict__ xij,
                                float* __restrict__ out,
                                int B) {
    __shared__ float ws_u[D * D];                 // transposed
    __shared__ float ws_i[D * D];
    __shared__ float su[SAMPLES_PER_BLOCK][D];
    __shared__ float si[SAMPLES_PER_BLOCK][D];

    const int tid = threadIdx.x;
    for (int idx = tid; idx < D * D; idx += blockDim.x) {
        int d = idx >> 6, k = idx & 63;
        ws_u[k * D + d] = w_user[idx];
        ws_i[k * D + d] = w_item[idx];
    }

    const int w    = tid >> 5;
    const int lane = tid & 31;
    const int s    = blockIdx.x * SAMPLES_PER_BLOCK + w;

    int item = 0;
    if (s < B) {
        int urow = users[s];
        item = items[s];
        int irow = N_USERS + item;

        long uo = (long)urow * DH + lane;
        long io = (long)irow * DH + lane;
        float2 u0 = *(const float2*)&emb_user[(long)urow * D + 2 * lane];
        float2 i0 = *(const float2*)&emb_item[(long)item * D + 2 * lane];
        float2 u1 = __half22float2(g_h1[uo]);
        float2 u2 = __half22float2(g_h2[uo]);
        float2 u3 = __half22float2(g_h3[uo]);
        float2 i1 = __half22float2(g_h1[io]);
        float2 i2 = __half22float2(g_h2[io]);
        float2 i3 = __half22float2(g_h3[io]);
        su[w][2 * lane]     = 0.25f * (u0.x + u1.x + u2.x + u3.x);
        su[w][2 * lane + 1] = 0.25f * (u0.y + u1.y + u2.y + u3.y);
        si[w][2 * lane]     = 0.25f * (i0.x + i1.x + i2.x + i3.x);
        si[w][2 * lane + 1] = 0.25f * (i0.y + i1.y + i2.y + i3.y);
    }
    __syncthreads();
    if (s >= B) return;

    float au0 = 0.f, au1 = 0.f, ai0 = 0.f, ai1 = 0.f;
    #pragma unroll
    for (int k = 0; k < D; k++) {
        float uk = su[w][k];
        float ik = si[w][k];
        au0 += ws_u[k * D + lane]      * uk;
        au1 += ws_u[k * D + lane + 32] * uk;
        ai0 += ws_i[k * D + lane]      * ik;
        ai1 += ws_i[k * D + lane + 32] * ik;
    }

    float m = fmaxf(au0, au1);
    #pragma unroll
    for (int off = 16; off > 0; off >>= 1)
        m = fmaxf(m, __shfl_xor_sync(0xffffffffu, m, off));
    float ex0 = expf(au0 - m);
    float ex1 = expf(au1 - m);
    float ssum = ex0 + ex1;
    float tdot = ex0 * sigmoidf_(ai0) + ex1 * sigmoidf_(ai1);
    #pragma unroll
    for (int off = 16; off > 0; off >>= 1) {
        ssum += __shfl_xor_sync(0xffffffffu, ssum, off);
        tdot += __shfl_xor_sync(0xffffffffu, tdot, off);
    }

    if (lane == 0) {
        float xe = (xij[s] > 0) ? xij_emb1[item] : xij_emb0[item];
        out[s] = (1.0f - HYPER_X) * (tdot / ssum) + HYPER_X * sigmoidf_(xe);
    }
}

// ---------------------------------------------------------------------------
// kernel_launch
// ---------------------------------------------------------------------------
extern "C" void kernel_launch(void* const* d_in, const int* in_sizes, int n_in,
                              void* d_out, int out_size) {
    const float* emb_user = (const float*)d_in[0];
    const float* emb_item = (const float*)d_in[1];
    const float* w_user   = (const float*)d_in[2];
    const float* w_item   = (const float*)d_in[3];
    const float* xij_emb1 = (const float*)d_in[4];
    const float* xij_emb0 = (const float*)d_in[5];
    const float* g_val    = (const float*)d_in[6];
    const int*   g_row    = (const int*)d_in[7];
    const int*   g_col    = (const int*)d_in[8];
    const int*   users    = (const int*)d_in[9];
    const int*   items    = (const int*)d_in[10];
    const int*   xij      = (const int*)d_in[11];
    float*       out      = (float*)d_out;

    const int nnz = in_sizes[6];
    const int B   = in_sizes[9];

    __half2 *h0, *h1, *h2, *h3;
    cudaGetSymbolAddress((void**)&h0, g_h0);
    cudaGetSymbolAddress((void**)&h1, g_h1);
    cudaGetSymbolAddress((void**)&h2, g_h2);
    cudaGetSymbolAddress((void**)&h3, g_h3);

    convert_zero_kernel<<<2048, 256>>>((const float2*)emb_user,
                                       (const float2*)emb_item);
    const int qblocks = (nnz / 4 + 255) / 256 + 1;
    mark_hist_kernel<<<qblocks, 256>>>(users, items, B, g_row, nnz);
    scan_lookback_kernel<<<SCAN_NB, SCAN_BLK>>>();
    fill_kernel<<<qblocks, 256>>>(g_row, g_col, g_val, nnz);

    const int warps_per_block = 8;                 // 256 threads
    const int sblocks = (N_TOTAL + warps_per_block - 1) / warps_per_block;
    spmm_h_kernel<<<sblocks, 256>>>(h0, h1);
    spmm_h_kernel<<<sblocks, 256>>>(h1, h2);
    const int lblocks = (MAX_SAMPLED + warps_per_block - 1) / warps_per_block;
    spmm_list_kernel<<<lblocks, 256>>>(h2, h3);

    const int eblocks = (B + SAMPLES_PER_BLOCK - 1) / SAMPLES_PER_BLOCK;
    epilogue_kernel<<<eblocks, 256>>>(emb_user, emb_item, w_user, w_item,
                                      xij_emb1, xij_emb0, users, items, xij,
                                      out, B);
}

// round 14
// speedup vs baseline: 1.1418x; 1.1418x over previous
#include <cuda_runtime.h>
#include <cuda_fp16.h>

#define N_USERS 100000
#define N_ITEMS 50000
#define N_TOTAL (N_USERS + N_ITEMS)
#define D 64
#define DH 32                 // half2 per row
#define HYPER_X 0.5f
#define MAX_NNZ 2000000
#define MAX_SAMPLED 32768
#define SCAN_BLK 1024
#define SCAN_NB ((N_TOTAL + SCAN_BLK - 1) / SCAN_BLK)   // 147

// fp16 feature tables: one 64-dim row = 32 half2 = 128B = one L2 line
__device__ __half2 g_h0[N_TOTAL * DH];   // converted input embeddings
__device__ __half2 g_h1[N_TOTAL * DH];
__device__ __half2 g_h2[N_TOTAL * DH];
__device__ __half2 g_h3[N_TOTAL * DH];

// CSR scratch. INVARIANT: g_deg, g_flag, g_blocksum, g_rowcount are ZERO at
// kernel_launch entry — zero-initialized at module load, and re-zeroed by
// cleanup_kernel at the end of every launch (graph-replay safe).
__device__ int  g_deg[N_TOTAL];
__device__ int  g_offs[N_TOTAL + 1];
__device__ int  g_rank[MAX_NNZ];         // per-edge within-row rank (from hist atomics)
__device__ int  g_blocksum[SCAN_NB];     // lookback slots: 0 = not ready, else agg+1
__device__ __align__(16) int2 g_csr[MAX_NNZ];   // {col, float_as_int(val)}

// sampled-row dedup for masked layer 3
__device__ int g_flag[N_TOTAL];
__device__ int g_rowlist[MAX_SAMPLED];
__device__ int g_rowcount;

// ---------------------------------------------------------------------------
// FUSED: fp32->fp16 embedding convert + sampled-row mark + degree histogram.
// deg/flag are guaranteed zero at entry (see invariant above), so no
// zeroing pass is needed and conversion overlaps the histogram atomics.
// ---------------------------------------------------------------------------
__global__ void convert_mark_hist_kernel(const float2* __restrict__ eu,
                                         const float2* __restrict__ ei,
                                         const int* __restrict__ users,
                                         const int* __restrict__ items, int B,
                                         const int* __restrict__ row, int nnz) {
    const int i = blockIdx.x * blockDim.x + threadIdx.x;
    const int nthreads = gridDim.x * blockDim.x;

    // mark sampled rows (dedup)
    if (i < B) {
        int u = users[i];
        if (atomicExch(&g_flag[u], 1) == 0) {
            int p = atomicAdd(&g_rowcount, 1);
            g_rowlist[p] = u;
        }
        int it = N_USERS + items[i];
        if (atomicExch(&g_flag[it], 1) == 0) {
            int p = atomicAdd(&g_rowcount, 1);
            g_rowlist[p] = it;
        }
    }

    // degree histogram, 4 edges/thread, rank captured from the atomic return
    int base = 4 * i;
    if (base + 3 < nnz) {
        int4 r4 = ((const int4*)row)[i];
        int4 k4;
        k4.x = atomicAdd(&g_deg[r4.x], 1);
        k4.y = atomicAdd(&g_deg[r4.y], 1);
        k4.z = atomicAdd(&g_deg[r4.z], 1);
        k4.w = atomicAdd(&g_deg[r4.w], 1);
        ((int4*)g_rank)[i] = k4;
    } else {
        for (int e = base; e < nnz; e++)
            g_rank[e] = atomicAdd(&g_deg[row[e]], 1);
    }

    // fp32 -> half2 conversion (grid-stride; overlaps the atomics above)
    const int total = N_TOTAL * DH;
    for (int k = i; k < total; k += nthreads) {
        float2 v = (k < N_USERS * DH) ? __ldg(&eu[k]) : __ldg(&ei[k - N_USERS * DH]);
        g_h0[k] = __floats2half2_rn(v.x, v.y);
    }
}

// ---------------------------------------------------------------------------
// single-kernel exclusive scan with decoupled lookback (147 blocks, 1 wave)
// ---------------------------------------------------------------------------
__device__ __forceinline__ int block_exscan(int v, int* sh) {
    int lane = threadIdx.x & 31, wid = threadIdx.x >> 5;
    int incl = v;
    #pragma unroll
    for (int o = 1; o < 32; o <<= 1) {
        int n = __shfl_up_sync(0xffffffffu, incl, o);
        if (lane >= o) incl += n;
    }
    if (lane == 31) sh[wid] = incl;
    __syncthreads();
    if (wid == 0) {
        int w = sh[lane];
        #pragma unroll
        for (int o = 1; o < 32; o <<= 1) {
            int n = __shfl_up_sync(0xffffffffu, w, o);
            if (lane >= o) w += n;
        }
        sh[lane] = w;
    }
    __syncthreads();
    int warpoff = (wid > 0) ? sh[wid - 1] : 0;
    return warpoff + incl - v;
}

__global__ void scan_lookback_kernel() {
    __shared__ int sh[32];
    __shared__ int base_sh;
    const int t = threadIdx.x;
    const int i = blockIdx.x * SCAN_BLK + t;
    int v = (i < N_TOTAL) ? g_deg[i] : 0;
    int ex = block_exscan(v, sh);

    if (t == SCAN_BLK - 1) {
        atomicExch(&g_blocksum[blockIdx.x], ex + v + 1);
    }
    if (t == 0) base_sh = 0;
    __syncthreads();

    if (t < blockIdx.x) {
        int a;
        do { a = atomicAdd(&g_blocksum[t], 0); } while (a == 0);
        atomicAdd(&base_sh, a - 1);
    }
    __syncthreads();

    int exg = ex + base_sh;
    if (i < N_TOTAL) {
        g_offs[i] = exg;
        if (i == N_TOTAL - 1) g_offs[N_TOTAL] = exg + v;
    }
}

// ---------------------------------------------------------------------------
// CSR fill, ATOMIC-FREE: pos = offs[row] + rank (rank captured during hist).
// ---------------------------------------------------------------------------
__global__ void fill_kernel(const int* __restrict__ row,
                            const int* __restrict__ col,
                            const float* __restrict__ val, int nnz) {
    int t = blockIdx.x * blockDim.x + threadIdx.x;
    int base = 4 * t;
    if (base + 3 < nnz) {
        int4   r4 = ((const int4*)row)[t];
        int4   c4 = ((const int4*)col)[t];
        float4 v4 = ((const float4*)val)[t];
        int4   k4 = ((const int4*)g_rank)[t];
        int p0 = __ldg(&g_offs[r4.x]) + k4.x;
        int p1 = __ldg(&g_offs[r4.y]) + k4.y;
        int p2 = __ldg(&g_offs[r4.z]) + k4.z;
        int p3 = __ldg(&g_offs[r4.w]) + k4.w;
        g_csr[p0] = make_int2(c4.x, __float_as_int(v4.x));
        g_csr[p1] = make_int2(c4.y, __float_as_int(v4.y));
        g_csr[p2] = make_int2(c4.z, __float_as_int(v4.z));
        g_csr[p3] = make_int2(c4.w, __float_as_int(v4.w));
    } else {
        for (int e = base; e < nnz; e++) {
            int p = __ldg(&g_offs[row[e]]) + g_rank[e];
            g_csr[p] = make_int2(col[e], __float_as_int(val[e]));
        }
    }
}

// ---------------------------------------------------------------------------
// cleanup: restore the zeroed-state invariant for the next graph replay.
// ---------------------------------------------------------------------------
__global__ void cleanup_kernel() {
    int i = blockIdx.x * blockDim.x + threadIdx.x;
    if (i < N_TOTAL) { g_deg[i] = 0; g_flag[i] = 0; }
    if (i < SCAN_NB) g_blocksum[i] = 0;
    if (i == 0) g_rowcount = 0;
}

// ---------------------------------------------------------------------------
// SpMM (fp16 storage, fp32 accumulate): 1 warp per row, one half2 per lane.
// Plain x2 loop + scalar tail — the empirically optimal form (R9/R12).
// ---------------------------------------------------------------------------
__device__ __forceinline__ void spmm_row_half(
        int r, int lane,
        const __half2* __restrict__ x, __half2* __restrict__ y) {
    const int beg = g_offs[r];
    const int end = g_offs[r + 1];

    float ax = 0.f, ay = 0.f;
    int j = beg;
    for (; j + 1 < end; j += 2) {
        int2 m0 = g_csr[j];
        int2 m1 = g_csr[j + 1];
        float2 x0 = __half22float2(x[(long)m0.x * DH + lane]);
        float2 x1 = __half22float2(x[(long)m1.x * DH + lane]);
        float v0 = __int_as_float(m0.y);
        float v1 = __int_as_float(m1.y);
        ax += v0 * x0.x; ay += v0 * x0.y;
        ax += v1 * x1.x; ay += v1 * x1.y;
    }
    if (j < end) {
        int2 m = g_csr[j];
        float2 xv = __half22float2(x[(long)m.x * DH + lane]);
        float v = __int_as_float(m.y);
        ax += v * xv.x; ay += v * xv.y;
    }
    y[(long)r * DH + lane] = __floats2half2_rn(ax, ay);
}

__global__ void spmm_h_kernel(const __half2* __restrict__ x,
                              __half2* __restrict__ y) {
    const int lane = threadIdx.x & 31;
    const int r = (blockIdx.x * blockDim.x + threadIdx.x) >> 5;
    if (r >= N_TOTAL) return;
    spmm_row_half(r, lane, x, y);
}

// layer 3: only sampled rows
__global__ void spmm_list_kernel(const __half2* __restrict__ x,
                                 __half2* __restrict__ y) {
    const int lane = threadIdx.x & 31;
    const int idx = (blockIdx.x * blockDim.x + threadIdx.x) >> 5;
    if (idx >= g_rowcount) return;
    const int r = g_rowlist[idx];
    spmm_row_half(r, lane, x, y);
}

// ---------------------------------------------------------------------------
// Epilogue: e0 from fp32 inputs (exact), e1..e3 from half tables.
// ---------------------------------------------------------------------------
#define SAMPLES_PER_BLOCK 8

__device__ __forceinline__ float sigmoidf_(float x) {
    return 1.0f / (1.0f + expf(-x));
}

__global__ void epilogue_kernel(const float* __restrict__ emb_user,
                                const float* __restrict__ emb_item,
                                const float* __restrict__ w_user,
                                const float* __restrict__ w_item,
                                const float* __restrict__ xij_emb1,
                                const float* __restrict__ xij_emb0,
                                const int* __restrict__ users,
                                const int* __restrict__ items,
                                const int* __restrict__ xij,
                                float* __restrict__ out,
                                int B) {
    __shared__ float ws_u[D * D];                 // transposed
    __shared__ float ws_i[D * D];
    __shared__ float su[SAMPLES_PER_BLOCK][D];
    __shared__ float si[SAMPLES_PER_BLOCK][D];

    const int tid = threadIdx.x;
    for (int idx = tid; idx < D * D; idx += blockDim.x) {
        int d = idx >> 6, k = idx & 63;
        ws_u[k * D + d] = w_user[idx];
        ws_i[k * D + d] = w_item[idx];
    }

    const int w    = tid >> 5;
    const int lane = tid & 31;
    const int s    = blockIdx.x * SAMPLES_PER_BLOCK + w;

    int item = 0;
    if (s < B) {
        int urow = users[s];
        item = items[s];
        int irow = N_USERS + item;

        long uo = (long)urow * DH + lane;
        long io = (long)irow * DH + lane;
        float2 u0 = *(const float2*)&emb_user[(long)urow * D + 2 * lane];
        float2 i0 = *(const float2*)&emb_item[(long)item * D + 2 * lane];
        float2 u1 = __half22float2(g_h1[uo]);
        float2 u2 = __half22float2(g_h2[uo]);
        float2 u3 = __half22float2(g_h3[uo]);
        float2 i1 = __half22float2(g_h1[io]);
        float2 i2 = __half22float2(g_h2[io]);
        float2 i3 = __half22float2(g_h3[io]);
        su[w][2 * lane]     = 0.25f * (u0.x + u1.x + u2.x + u3.x);
        su[w][2 * lane + 1] = 0.25f * (u0.y + u1.y + u2.y + u3.y);
        si[w][2 * lane]     = 0.25f * (i0.x + i1.x + i2.x + i3.x);
        si[w][2 * lane + 1] = 0.25f * (i0.y + i1.y + i2.y + i3.y);
    }
    __syncthreads();
    if (s >= B) return;

    float au0 = 0.f, au1 = 0.f, ai0 = 0.f, ai1 = 0.f;
    #pragma unroll
    for (int k = 0; k < D; k++) {
        float uk = su[w][k];
        float ik = si[w][k];
        au0 += ws_u[k * D + lane]      * uk;
        au1 += ws_u[k * D + lane + 32] * uk;
        ai0 += ws_i[k * D + lane]      * ik;
        ai1 += ws_i[k * D + lane + 32] * ik;
    }

    float m = fmaxf(au0, au1);
    #pragma unroll
    for (int off = 16; off > 0; off >>= 1)
        m = fmaxf(m, __shfl_xor_sync(0xffffffffu, m, off));
    float ex0 = expf(au0 - m);
    float ex1 = expf(au1 - m);
    float ssum = ex0 + ex1;
    float tdot = ex0 * sigmoidf_(ai0) + ex1 * sigmoidf_(ai1);
    #pragma unroll
    for (int off = 16; off > 0; off >>= 1) {
        ssum += __shfl_xor_sync(0xffffffffu, ssum, off);
        tdot += __shfl_xor_sync(0xffffffffu, tdot, off);
    }

    if (lane == 0) {
        float xe = (xij[s] > 0) ? xij_emb1[item] : xij_emb0[item];
        out[s] = (1.0f - HYPER_X) * (tdot / ssum) + HYPER_X * sigmoidf_(xe);
    }
}

// ---------------------------------------------------------------------------
// kernel_launch
// ---------------------------------------------------------------------------
extern "C" void kernel_launch(void* const* d_in, const int* in_sizes, int n_in,
                              void* d_out, int out_size) {
    const float* emb_user = (const float*)d_in[0];
    const float* emb_item = (const float*)d_in[1];
    const float* w_user   = (const float*)d_in[2];
    const float* w_item   = (const float*)d_in[3];
    const float* xij_emb1 = (const float*)d_in[4];
    const float* xij_emb0 = (const float*)d_in[5];
    const float* g_val    = (const float*)d_in[6];
    const int*   g_row    = (const int*)d_in[7];
    const int*   g_col    = (const int*)d_in[8];
    const int*   users    = (const int*)d_in[9];
    const int*   items    = (const int*)d_in[10];
    const int*   xij      = (const int*)d_in[11];
    float*       out      = (float*)d_out;

    const int nnz = in_sizes[6];
    const int B   = in_sizes[9];

    __half2 *h0, *h1, *h2, *h3;
    cudaGetSymbolAddress((void**)&h0, g_h0);
    cudaGetSymbolAddress((void**)&h1, g_h1);
    cudaGetSymbolAddress((void**)&h2, g_h2);
    cudaGetSymbolAddress((void**)&h3, g_h3);

    const int qblocks = (nnz / 4 + 255) / 256 + 1;
    convert_mark_hist_kernel<<<qblocks, 256>>>((const float2*)emb_user,
                                               (const float2*)emb_item,
                                               users, items, B, g_row, nnz);
    scan_lookback_kernel<<<SCAN_NB, SCAN_BLK>>>();
    fill_kernel<<<qblocks, 256>>>(g_row, g_col, g_val, nnz);

    const int warps_per_block = 8;                 // 256 threads
    const int sblocks = (N_TOTAL + warps_per_block - 1) / warps_per_block;
    spmm_h_kernel<<<sblocks, 256>>>(h0, h1);
    spmm_h_kernel<<<sblocks, 256>>>(h1, h2);
    const int lblocks = (MAX_SAMPLED + warps_per_block - 1) / warps_per_block;
    spmm_list_kernel<<<lblocks, 256>>>(h2, h3);

    const int eblocks = (B + SAMPLES_PER_BLOCK - 1) / SAMPLES_PER_BLOCK;
    epilogue_kernel<<<eblocks, 256>>>(emb_user, emb_item, w_user, w_item,
                                      xij_emb1, xij_emb0, users, items, xij,
                                      out, B);

    // restore zeroed-state invariant for the next replay
    cleanup_kernel<<<(N_TOTAL + 255) / 256, 256>>>();
}